// round 5
// baseline (speedup 1.0000x reference)
#include <cuda_runtime.h>

// ---------------------------------------------------------------------------
// GCN: 3x (GEMM 128x128 + CSR gather-aggregate) + mean-pool + linear head.
// Scratch lives in one __device__ global (no allocations anywhere).
// ---------------------------------------------------------------------------

static constexpr int MAXN = 65536;
static constexpr int MAXE = 2000000;

static constexpr size_t SZ_FEAT = (size_t)MAXN * 128 * 4;   // N x 128 floats
static constexpr size_t SZ_EDGE = (size_t)MAXE * 4;
static constexpr size_t SZ_IDX  = (size_t)(MAXN + 16) * 4;

static constexpr size_t OFF_T     = 0;
static constexpr size_t OFF_A     = OFF_T + SZ_FEAT;
static constexpr size_t OFF_NRM1  = OFF_A + SZ_FEAT;
static constexpr size_t OFF_NRM   = OFF_NRM1 + SZ_EDGE;
static constexpr size_t OFF_COL   = OFF_NRM + SZ_EDGE;
static constexpr size_t OFF_ROWP  = OFF_COL + SZ_EDGE;
static constexpr size_t OFF_CNT   = OFF_ROWP + SZ_IDX;
static constexpr size_t OFF_DEG   = OFF_CNT + SZ_IDX;
static constexpr size_t OFF_DINV1 = OFF_DEG + SZ_IDX;
static constexpr size_t OFF_DINV  = OFF_DINV1 + SZ_IDX;
static constexpr size_t OFF_POOL  = OFF_DINV + SZ_IDX;
static constexpr size_t OFF_PCNT  = OFF_POOL + (size_t)512 * 128 * 4;
static constexpr size_t SCRATCH_BYTES = OFF_PCNT + 512 * 4;

__device__ __align__(16) unsigned char g_scratch[SCRATCH_BYTES];

// --------------------------- CSR build ------------------------------------

__global__ void k_zero_pre(float* deg, int* cnt, int n) {
    int i = blockIdx.x * blockDim.x + threadIdx.x;
    if (i < n) { deg[i] = 0.f; cnt[i] = 0; }
}

__global__ void k_hist(const int* __restrict__ dst, const float* __restrict__ ew,
                       float* deg, int* cnt, int E) {
    int e = blockIdx.x * blockDim.x + threadIdx.x;
    if (e < E) {
        int d = dst[e];
        atomicAdd(&deg[d], ew[e]);
        atomicAdd(&cnt[d], 1);
    }
}

// Single-block exclusive scan over cnt -> rowptr; also zeroes cnt for refill.
__global__ void k_scan(int* cnt, int* rowptr, int n) {
    __shared__ int wsum[32];
    __shared__ int carry;
    int tid = threadIdx.x;
    if (tid == 0) carry = 0;
    __syncthreads();
    for (int base = 0; base < n; base += 1024) {
        int i = base + tid;
        int v = (i < n) ? cnt[i] : 0;
        int x = v;
        #pragma unroll
        for (int o = 1; o < 32; o <<= 1) {
            int t = __shfl_up_sync(0xffffffffu, x, o);
            if ((tid & 31) >= o) x += t;
        }
        if ((tid & 31) == 31) wsum[tid >> 5] = x;
        __syncthreads();
        if (tid < 32) {
            int s = wsum[tid];
            #pragma unroll
            for (int o = 1; o < 32; o <<= 1) {
                int t = __shfl_up_sync(0xffffffffu, s, o);
                if (tid >= o) s += t;
            }
            wsum[tid] = s;
        }
        __syncthreads();
        int pre = (tid >= 32) ? wsum[(tid >> 5) - 1] : 0;
        int incl = x + pre;
        if (i < n) { rowptr[i] = carry + incl - v; cnt[i] = 0; }
        __syncthreads();
        if (tid == 1023) carry += incl;
        __syncthreads();
    }
    if (tid == 0) rowptr[n] = carry;
}

__global__ void k_dinv(const float* __restrict__ deg, float* dinv1, float* dinv, int n) {
    int i = blockIdx.x * blockDim.x + threadIdx.x;
    if (i < n) {
        float d = deg[i];
        dinv1[i] = rsqrtf(d + 2.0f);  // improved self-loop fill = 2.0
        dinv[i]  = rsqrtf(d + 1.0f);
    }
}

__global__ void k_fill(const int* __restrict__ src, const int* __restrict__ dst,
                       const float* __restrict__ ew, const int* __restrict__ rowptr,
                       int* cnt, const float* __restrict__ dinv1,
                       const float* __restrict__ dinv,
                       int* col, float* nrm1, float* nrm, int E) {
    int e = blockIdx.x * blockDim.x + threadIdx.x;
    if (e >= E) return;
    int s = src[e], d = dst[e];
    int pos = rowptr[d] + atomicAdd(&cnt[d], 1);
    float w = ew[e];
    col[pos]  = s;
    nrm1[pos] = dinv1[s] * w * dinv1[d];
    nrm[pos]  = dinv[s]  * w * dinv[d];
}

// --------------------------- GEMM [N,128] @ [128,128] ----------------------
// 64 rows x 128 cols per block, 256 threads, W(64KB)+Xtile(32KB) in smem.

__global__ void k_gemm128(const float* __restrict__ A, const float* __restrict__ W,
                          float* __restrict__ T, int N) {
    extern __shared__ float sm[];
    float4* sW4 = (float4*)sm;             // 4096 float4 = 64 KB
    float4* sX4 = (float4*)(sm + 16384);   // 2048 float4 = 32 KB
    int tid  = threadIdx.x;
    int row0 = blockIdx.x * 64;

    const float4* W4 = (const float4*)W;
    #pragma unroll 4
    for (int i = tid; i < 4096; i += 256) sW4[i] = W4[i];

    const float4* A4 = (const float4*)A;
    #pragma unroll 2
    for (int i = tid; i < 2048; i += 256) {
        int r = i >> 5, c = i & 31;
        float4 v = make_float4(0.f, 0.f, 0.f, 0.f);
        if (row0 + r < N) v = A4[(size_t)(row0 + r) * 32 + c];
        sX4[i] = v;
    }
    __syncthreads();

    int tx = tid & 31;   // column group: cols 4*tx..4*tx+3
    int ty = tid >> 5;   // rows j*8 + ty
    float4 acc[8];
    #pragma unroll
    for (int j = 0; j < 8; j++) acc[j] = make_float4(0.f, 0.f, 0.f, 0.f);

    for (int k4 = 0; k4 < 32; k4++) {
        float4 w0 = sW4[(4 * k4 + 0) * 32 + tx];
        float4 w1 = sW4[(4 * k4 + 1) * 32 + tx];
        float4 w2 = sW4[(4 * k4 + 2) * 32 + tx];
        float4 w3 = sW4[(4 * k4 + 3) * 32 + tx];
        #pragma unroll
        for (int j = 0; j < 8; j++) {
            float4 xv = sX4[(j * 8 + ty) * 32 + k4];
            acc[j].x += xv.x * w0.x + xv.y * w1.x + xv.z * w2.x + xv.w * w3.x;
            acc[j].y += xv.x * w0.y + xv.y * w1.y + xv.z * w2.y + xv.w * w3.y;
            acc[j].z += xv.x * w0.z + xv.y * w1.z + xv.z * w2.z + xv.w * w3.z;
            acc[j].w += xv.x * w0.w + xv.y * w1.w + xv.z * w2.w + xv.w * w3.w;
        }
    }

    float4* T4 = (float4*)T;
    #pragma unroll
    for (int j = 0; j < 8; j++) {
        int r = row0 + j * 8 + ty;
        if (r < N) T4[(size_t)r * 32 + tx] = acc[j];
    }
}

// --------------------- CSR gather aggregation (warp/node) ------------------
// out[v] = bias + fill*dinv[v]^2 * T[v] + sum_e nrm[e] * T[col[e]]; opt. ReLU.

__global__ void k_gather(const float* __restrict__ T, const int* __restrict__ rowptr,
                         const int* __restrict__ col, const float* __restrict__ nrm,
                         const float* __restrict__ dinv, float fill,
                         const float* __restrict__ bias, float* __restrict__ out,
                         int N, int do_relu) {
    int w = (int)((blockIdx.x * (unsigned)blockDim.x + threadIdx.x) >> 5);
    if (w >= N) return;
    int lane = threadIdx.x & 31;
    const float4* T4 = (const float4*)T;

    float dv = __ldg(&dinv[w]);
    float sc = dv * dv * fill;
    float4 b4 = __ldg(&((const float4*)bias)[lane]);
    float4 tv = T4[(size_t)w * 32 + lane];
    float ax = b4.x + sc * tv.x;
    float ay = b4.y + sc * tv.y;
    float az = b4.z + sc * tv.z;
    float aw = b4.w + sc * tv.w;

    int e   = __ldg(&rowptr[w]);
    int end = __ldg(&rowptr[w + 1]);
    for (; e + 3 < end; e += 4) {
        int c0 = __ldg(&col[e]), c1 = __ldg(&col[e + 1]);
        int c2 = __ldg(&col[e + 2]), c3 = __ldg(&col[e + 3]);
        float w0 = __ldg(&nrm[e]), w1 = __ldg(&nrm[e + 1]);
        float w2 = __ldg(&nrm[e + 2]), w3 = __ldg(&nrm[e + 3]);
        float4 t0 = T4[(size_t)c0 * 32 + lane];
        float4 t1 = T4[(size_t)c1 * 32 + lane];
        float4 t2 = T4[(size_t)c2 * 32 + lane];
        float4 t3 = T4[(size_t)c3 * 32 + lane];
        ax += w0 * t0.x + w1 * t1.x + w2 * t2.x + w3 * t3.x;
        ay += w0 * t0.y + w1 * t1.y + w2 * t2.y + w3 * t3.y;
        az += w0 * t0.z + w1 * t1.z + w2 * t2.z + w3 * t3.z;
        aw += w0 * t0.w + w1 * t1.w + w2 * t2.w + w3 * t3.w;
    }
    for (; e < end; e++) {
        int c = __ldg(&col[e]);
        float ww = __ldg(&nrm[e]);
        float4 t = T4[(size_t)c * 32 + lane];
        ax += ww * t.x; ay += ww * t.y; az += ww * t.z; aw += ww * t.w;
    }
    if (do_relu) {
        ax = fmaxf(ax, 0.f); ay = fmaxf(ay, 0.f);
        az = fmaxf(az, 0.f); aw = fmaxf(aw, 0.f);
    }
    ((float4*)out)[(size_t)w * 32 + lane] = make_float4(ax, ay, az, aw);
}

// --------------------------- Mean pool + head ------------------------------

__global__ void k_zero_pool(float* pool, float* pcnt, int Bg) {
    int i = blockIdx.x * blockDim.x + threadIdx.x;
    if (i < Bg * 128) pool[i] = 0.f;
    if (i < Bg) pcnt[i] = 0.f;
}

// batch[] is sorted: accumulate runs locally, flush on segment change.
__global__ void k_pool(const float* __restrict__ A, const int* __restrict__ batch,
                       float* pool, float* pcnt, int N) {
    int w = (int)((blockIdx.x * (unsigned)blockDim.x + threadIdx.x) >> 5);
    int lane = threadIdx.x & 31;
    int v0 = w * 64;
    if (v0 >= N) return;
    int vend = min(v0 + 64, N);
    const float4* A4 = (const float4*)A;
    int curb = __ldg(&batch[v0]);
    float ax = 0.f, ay = 0.f, az = 0.f, aw = 0.f, cnt = 0.f;
    for (int v = v0; v < vend; v++) {
        int b = __ldg(&batch[v]);
        if (b != curb) {
            float* p = pool + (size_t)curb * 128 + lane * 4;
            atomicAdd(p, ax); atomicAdd(p + 1, ay);
            atomicAdd(p + 2, az); atomicAdd(p + 3, aw);
            if (lane == 0) atomicAdd(&pcnt[curb], cnt);
            ax = ay = az = aw = cnt = 0.f;
            curb = b;
        }
        float4 t = A4[(size_t)v * 32 + lane];
        ax += t.x; ay += t.y; az += t.z; aw += t.w;
        cnt += 1.f;
    }
    float* p = pool + (size_t)curb * 128 + lane * 4;
    atomicAdd(p, ax); atomicAdd(p + 1, ay);
    atomicAdd(p + 2, az); atomicAdd(p + 3, aw);
    if (lane == 0) atomicAdd(&pcnt[curb], cnt);
}

__global__ void k_final(const float* __restrict__ pool, const float* __restrict__ pcnt,
                        const float* __restrict__ Wlin, const float* __restrict__ blin,
                        float* __restrict__ out) {
    int b = blockIdx.x;
    int lane = threadIdx.x;
    float inv = 1.f / fmaxf(__ldg(&pcnt[b]), 1.f);
    float4 p = __ldg(&((const float4*)pool)[b * 32 + lane]);
    p.x *= inv; p.y *= inv; p.z *= inv; p.w *= inv;
    int f = lane * 4;
    #pragma unroll
    for (int c = 0; c < 10; c++) {
        float s = p.x * __ldg(&Wlin[f * 10 + c])
                + p.y * __ldg(&Wlin[(f + 1) * 10 + c])
                + p.z * __ldg(&Wlin[(f + 2) * 10 + c])
                + p.w * __ldg(&Wlin[(f + 3) * 10 + c]);
        #pragma unroll
        for (int o = 16; o; o >>= 1) s += __shfl_down_sync(0xffffffffu, s, o);
        if (lane == 0) out[b * 10 + c] = s + __ldg(&blin[c]);
    }
}

// --------------------------------- launch ----------------------------------

extern "C" void kernel_launch(void* const* d_in, const int* in_sizes, int n_in,
                              void* d_out, int out_size) {
    const float* x     = (const float*)d_in[0];
    const int*   ei    = (const int*)d_in[1];
    const int*   batch = (const int*)d_in[2];
    const float* ew    = (const float*)d_in[3];
    const float* W1 = (const float*)d_in[4];  const float* b1 = (const float*)d_in[5];
    const float* W2 = (const float*)d_in[6];  const float* b2 = (const float*)d_in[7];
    const float* W3 = (const float*)d_in[8];  const float* b3 = (const float*)d_in[9];
    const float* Wlin = (const float*)d_in[10];
    const float* blin = (const float*)d_in[11];

    int N  = in_sizes[2];        // batch has shape (N,)
    int E  = in_sizes[3];        // edge_weight has shape (E,)
    int Bg = out_size / 10;
    const int* src = ei;
    const int* dst = ei + E;

    unsigned char* base = nullptr;
    cudaGetSymbolAddress((void**)&base, g_scratch);
    float* T      = (float*)(base + OFF_T);
    float* A      = (float*)(base + OFF_A);
    float* nrm1   = (float*)(base + OFF_NRM1);
    float* nrm    = (float*)(base + OFF_NRM);
    int*   col    = (int*)(base + OFF_COL);
    int*   rowptr = (int*)(base + OFF_ROWP);
    int*   cnt    = (int*)(base + OFF_CNT);
    float* deg    = (float*)(base + OFF_DEG);
    float* dinv1  = (float*)(base + OFF_DINV1);
    float* dinv   = (float*)(base + OFF_DINV);
    float* pool   = (float*)(base + OFF_POOL);
    float* pcnt   = (float*)(base + OFF_PCNT);

    cudaFuncSetAttribute(k_gemm128, cudaFuncAttributeMaxDynamicSharedMemorySize, 98304);

    const int tb = 256;

    // CSR build (shared across all 3 layers)
    k_zero_pre<<<(N + tb - 1) / tb, tb>>>(deg, cnt, N);
    k_hist<<<(E + tb - 1) / tb, tb>>>(dst, ew, deg, cnt, E);
    k_scan<<<1, 1024>>>(cnt, rowptr, N);
    k_dinv<<<(N + tb - 1) / tb, tb>>>(deg, dinv1, dinv, N);
    k_fill<<<(E + tb - 1) / tb, tb>>>(src, dst, ew, rowptr, cnt,
                                      dinv1, dinv, col, nrm1, nrm, E);

    int gemm_blocks = (N + 63) / 64;
    int gat_blocks  = (int)(((size_t)N * 32 + 255) / 256);

    // Layer 1 (improved: fill=2.0) + ReLU
    k_gemm128<<<gemm_blocks, 256, 98304>>>(x, W1, T, N);
    k_gather<<<gat_blocks, 256>>>(T, rowptr, col, nrm1, dinv1, 2.0f, b1, A, N, 1);
    // Layer 2 + ReLU
    k_gemm128<<<gemm_blocks, 256, 98304>>>(A, W2, T, N);
    k_gather<<<gat_blocks, 256>>>(T, rowptr, col, nrm, dinv, 1.0f, b2, A, N, 1);
    // Layer 3 (no ReLU)
    k_gemm128<<<gemm_blocks, 256, 98304>>>(A, W3, T, N);
    k_gather<<<gat_blocks, 256>>>(T, rowptr, col, nrm, dinv, 1.0f, b3, A, N, 0);

    // Mean pool over sorted batch ids, then linear head
    k_zero_pool<<<(Bg * 128 + tb - 1) / tb, tb>>>(pool, pcnt, Bg);
    int pw = (N + 63) / 64;
    k_pool<<<(pw * 32 + 255) / 256, 256>>>(A, batch, pool, pcnt, N);
    k_final<<<Bg, 32>>>(pool, pcnt, Wlin, blin, (float*)d_out);
}

// round 8
// speedup vs baseline: 1.1385x; 1.1385x over previous
#include <cuda_runtime.h>
#include <cuda_bf16.h>

// ---------------------------------------------------------------------------
// GCN: 3x (GEMM 128x128 fp32->bf16 + CSR gather-aggregate on bf16 features)
//      + mean-pool + linear head. Scratch in one __device__ global.
// ---------------------------------------------------------------------------

static constexpr int MAXN = 65536;
static constexpr int MAXE = 2000000;

static constexpr size_t SZ_FEAT   = (size_t)MAXN * 128 * 4;  // N x 128 fp32
static constexpr size_t SZ_FEAT_H = (size_t)MAXN * 128 * 2;  // N x 128 bf16
static constexpr size_t SZ_EREC   = (size_t)MAXE * 8;        // {col, nrm} per edge
static constexpr size_t SZ_IDX    = (size_t)(MAXN + 16) * 4;

static constexpr size_t OFF_T     = 0;                        // bf16 GEMM output
static constexpr size_t OFF_A     = OFF_T + SZ_FEAT_H;        // fp32 layer output
static constexpr size_t OFF_ED1   = OFF_A + SZ_FEAT;          // edge recs (layer1 norm)
static constexpr size_t OFF_ED    = OFF_ED1 + SZ_EREC;        // edge recs (layers 2-3)
static constexpr size_t OFF_ROWP  = OFF_ED + SZ_EREC;
static constexpr size_t OFF_CNT   = OFF_ROWP + SZ_IDX;
static constexpr size_t OFF_DEG   = OFF_CNT + SZ_IDX;
static constexpr size_t OFF_DINV1 = OFF_DEG + SZ_IDX;
static constexpr size_t OFF_DINV  = OFF_DINV1 + SZ_IDX;
static constexpr size_t OFF_POOL  = OFF_DINV + SZ_IDX;
static constexpr size_t OFF_PCNT  = OFF_POOL + (size_t)512 * 128 * 4;
static constexpr size_t SCRATCH_BYTES = OFF_PCNT + 512 * 4;

__device__ __align__(16) unsigned char g_scratch[SCRATCH_BYTES];

// --------------------------- CSR build ------------------------------------

__global__ void k_zero_pre(float* deg, int* cnt, int n, int npad) {
    int i = blockIdx.x * blockDim.x + threadIdx.x;
    if (i < n) deg[i] = 0.f;
    if (i < npad) cnt[i] = 0;
}

__global__ void k_hist(const int* __restrict__ dst, const float* __restrict__ ew,
                       float* deg, int* cnt, int E) {
    int e = blockIdx.x * blockDim.x + threadIdx.x;
    if (e < E) {
        int d = dst[e];
        atomicAdd(&deg[d], ew[e]);
        atomicAdd(&cnt[d], 1);
    }
}

// Single-block exclusive scan over cnt -> rowptr (int4 per thread); zeroes cnt.
__global__ void k_scan(int* cnt, int* rowptr, int n) {
    __shared__ int wsum[32];
    __shared__ int carry;
    int tid = threadIdx.x;
    if (tid == 0) carry = 0;
    __syncthreads();
    int n4 = (n + 3) >> 2;
    int4* cnt4 = (int4*)cnt;
    int4* rp4  = (int4*)rowptr;
    for (int base = 0; base < n4; base += 1024) {
        int i = base + tid;
        int4 v = (i < n4) ? cnt4[i] : make_int4(0, 0, 0, 0);
        int t = v.x + v.y + v.z + v.w;
        int x = t;
        #pragma unroll
        for (int o = 1; o < 32; o <<= 1) {
            int s = __shfl_up_sync(0xffffffffu, x, o);
            if ((tid & 31) >= o) x += s;
        }
        if ((tid & 31) == 31) wsum[tid >> 5] = x;
        __syncthreads();
        if (tid < 32) {
            int s = wsum[tid];
            #pragma unroll
            for (int o = 1; o < 32; o <<= 1) {
                int u = __shfl_up_sync(0xffffffffu, s, o);
                if (tid >= o) s += u;
            }
            wsum[tid] = s;
        }
        __syncthreads();
        int pre  = (tid >= 32) ? wsum[(tid >> 5) - 1] : 0;
        int excl = carry + pre + x - t;
        if (i < n4) {
            rp4[i]  = make_int4(excl, excl + v.x, excl + v.x + v.y,
                                excl + v.x + v.y + v.z);
            cnt4[i] = make_int4(0, 0, 0, 0);
        }
        __syncthreads();
        if (tid == 0) carry += wsum[31];
        __syncthreads();
    }
    if (tid == 0) rowptr[n] = carry;
}

__global__ void k_dinv(const float* __restrict__ deg, float* dinv1, float* dinv, int n) {
    int i = blockIdx.x * blockDim.x + threadIdx.x;
    if (i < n) {
        float d = deg[i];
        dinv1[i] = rsqrtf(d + 2.0f);  // improved self-loop fill = 2.0
        dinv[i]  = rsqrtf(d + 1.0f);
    }
}

__global__ void k_fill(const int* __restrict__ src, const int* __restrict__ dst,
                       const float* __restrict__ ew, const int* __restrict__ rowptr,
                       int* cnt, const float* __restrict__ dinv1,
                       const float* __restrict__ dinv,
                       int2* __restrict__ ed1, int2* __restrict__ ed, int E) {
    int e = blockIdx.x * blockDim.x + threadIdx.x;
    if (e >= E) return;
    int s = src[e], d = dst[e];
    int pos = rowptr[d] + atomicAdd(&cnt[d], 1);
    float w = ew[e];
    ed1[pos] = make_int2(s, __float_as_int(dinv1[s] * w * dinv1[d]));
    ed[pos]  = make_int2(s, __float_as_int(dinv[s]  * w * dinv[d]));
}

// --------------------------- GEMM [N,128] @ [128,128] ----------------------
// 64 rows x 128 cols per block, 256 threads, W(64KB)+Xtile(32KB) in smem.
// fp32 accumulate, bf16 output.

__global__ void k_gemm128(const float* __restrict__ A, const float* __restrict__ W,
                          __nv_bfloat16* __restrict__ T, int N) {
    extern __shared__ float sm[];
    float4* sW4 = (float4*)sm;             // 4096 float4 = 64 KB
    float4* sX4 = (float4*)(sm + 16384);   // 2048 float4 = 32 KB
    int tid  = threadIdx.x;
    int row0 = blockIdx.x * 64;

    const float4* W4 = (const float4*)W;
    #pragma unroll 4
    for (int i = tid; i < 4096; i += 256) sW4[i] = W4[i];

    const float4* A4 = (const float4*)A;
    #pragma unroll 2
    for (int i = tid; i < 2048; i += 256) {
        int r = i >> 5, c = i & 31;
        float4 v = make_float4(0.f, 0.f, 0.f, 0.f);
        if (row0 + r < N) v = A4[(size_t)(row0 + r) * 32 + c];
        sX4[i] = v;
    }
    __syncthreads();

    int tx = tid & 31;   // column group: cols 4*tx..4*tx+3
    int ty = tid >> 5;   // rows j*8 + ty
    float4 acc[8];
    #pragma unroll
    for (int j = 0; j < 8; j++) acc[j] = make_float4(0.f, 0.f, 0.f, 0.f);

    for (int k4 = 0; k4 < 32; k4++) {
        float4 w0 = sW4[(4 * k4 + 0) * 32 + tx];
        float4 w1 = sW4[(4 * k4 + 1) * 32 + tx];
        float4 w2 = sW4[(4 * k4 + 2) * 32 + tx];
        float4 w3 = sW4[(4 * k4 + 3) * 32 + tx];
        #pragma unroll
        for (int j = 0; j < 8; j++) {
            float4 xv = sX4[(j * 8 + ty) * 32 + k4];
            acc[j].x += xv.x * w0.x + xv.y * w1.x + xv.z * w2.x + xv.w * w3.x;
            acc[j].y += xv.x * w0.y + xv.y * w1.y + xv.z * w2.y + xv.w * w3.y;
            acc[j].z += xv.x * w0.z + xv.y * w1.z + xv.z * w2.z + xv.w * w3.z;
            acc[j].w += xv.x * w0.w + xv.y * w1.w + xv.z * w2.w + xv.w * w3.w;
        }
    }

    uint2* T2 = (uint2*)T;
    #pragma unroll
    for (int j = 0; j < 8; j++) {
        int r = row0 + j * 8 + ty;
        if (r < N) {
            __nv_bfloat162 h0 = __floats2bfloat162_rn(acc[j].x, acc[j].y);
            __nv_bfloat162 h1 = __floats2bfloat162_rn(acc[j].z, acc[j].w);
            uint2 o;
            o.x = *(unsigned*)&h0;
            o.y = *(unsigned*)&h1;
            T2[(size_t)r * 32 + tx] = o;
        }
    }
}

// --------------------- CSR gather aggregation (warp/node) ------------------
// out[v] = bias + fill*dinv[v]^2 * T[v] + sum_e nrm[e] * T[col[e]]; opt. ReLU.
// T is bf16 (256B/row), edge record = int2{col, nrm_bits} (8B).

__device__ __forceinline__ void bf8_to_f(uint2 t, float& x, float& y, float& z, float& w) {
    __nv_bfloat162 p0 = *(__nv_bfloat162*)&t.x;
    __nv_bfloat162 p1 = *(__nv_bfloat162*)&t.y;
    float2 f0 = __bfloat1622float2(p0);
    float2 f1 = __bfloat1622float2(p1);
    x = f0.x; y = f0.y; z = f1.x; w = f1.y;
}

__global__ void k_gather(const __nv_bfloat16* __restrict__ T,
                         const int* __restrict__ rowptr,
                         const int2* __restrict__ ed,
                         const float* __restrict__ dinv, float fill,
                         const float* __restrict__ bias, float* __restrict__ out,
                         int N, int do_relu) {
    int w = (int)((blockIdx.x * (unsigned)blockDim.x + threadIdx.x) >> 5);
    if (w >= N) return;
    int lane = threadIdx.x & 31;
    const uint2* T2 = (const uint2*)T;

    float dv = __ldg(&dinv[w]);
    float sc = dv * dv * fill;
    float4 b4 = __ldg(&((const float4*)bias)[lane]);
    float sx, sy, sz, sw;
    bf8_to_f(T2[(size_t)w * 32 + lane], sx, sy, sz, sw);
    float ax = b4.x + sc * sx;
    float ay = b4.y + sc * sy;
    float az = b4.z + sc * sz;
    float aw = b4.w + sc * sw;

    int e   = __ldg(&rowptr[w]);
    int end = __ldg(&rowptr[w + 1]);
    for (; e + 3 < end; e += 4) {
        int2 r0 = __ldg(&ed[e]);
        int2 r1 = __ldg(&ed[e + 1]);
        int2 r2 = __ldg(&ed[e + 2]);
        int2 r3 = __ldg(&ed[e + 3]);
        uint2 t0 = T2[(size_t)r0.x * 32 + lane];
        uint2 t1 = T2[(size_t)r1.x * 32 + lane];
        uint2 t2 = T2[(size_t)r2.x * 32 + lane];
        uint2 t3 = T2[(size_t)r3.x * 32 + lane];
        float w0 = __int_as_float(r0.y), w1 = __int_as_float(r1.y);
        float w2 = __int_as_float(r2.y), w3 = __int_as_float(r3.y);
        float fx, fy, fz, fw;
        bf8_to_f(t0, fx, fy, fz, fw);
        ax += w0 * fx; ay += w0 * fy; az += w0 * fz; aw += w0 * fw;
        bf8_to_f(t1, fx, fy, fz, fw);
        ax += w1 * fx; ay += w1 * fy; az += w1 * fz; aw += w1 * fw;
        bf8_to_f(t2, fx, fy, fz, fw);
        ax += w2 * fx; ay += w2 * fy; az += w2 * fz; aw += w2 * fw;
        bf8_to_f(t3, fx, fy, fz, fw);
        ax += w3 * fx; ay += w3 * fy; az += w3 * fz; aw += w3 * fw;
    }
    for (; e < end; e++) {
        int2 r = __ldg(&ed[e]);
        uint2 t = T2[(size_t)r.x * 32 + lane];
        float ww = __int_as_float(r.y);
        float fx, fy, fz, fw;
        bf8_to_f(t, fx, fy, fz, fw);
        ax += ww * fx; ay += ww * fy; az += ww * fz; aw += ww * fw;
    }
    if (do_relu) {
        ax = fmaxf(ax, 0.f); ay = fmaxf(ay, 0.f);
        az = fmaxf(az, 0.f); aw = fmaxf(aw, 0.f);
    }
    ((float4*)out)[(size_t)w * 32 + lane] = make_float4(ax, ay, az, aw);
}

// --------------------------- Mean pool + head ------------------------------

__global__ void k_zero_pool(float* pool, float* pcnt, int Bg) {
    int i = blockIdx.x * blockDim.x + threadIdx.x;
    if (i < Bg * 128) pool[i] = 0.f;
    if (i < Bg) pcnt[i] = 0.f;
}

// batch[] is sorted: accumulate runs locally, flush on segment change.
__global__ void k_pool(const float* __restrict__ A, const int* __restrict__ batch,
                       float* pool, float* pcnt, int N) {
    int w = (int)((blockIdx.x * (unsigned)blockDim.x + threadIdx.x) >> 5);
    int lane = threadIdx.x & 31;
    int v0 = w * 64;
    if (v0 >= N) return;
    int vend = min(v0 + 64, N);
    const float4* A4 = (const float4*)A;
    int curb = __ldg(&batch[v0]);
    float ax = 0.f, ay = 0.f, az = 0.f, aw = 0.f, cnt = 0.f;
    for (int v = v0; v < vend; v++) {
        int b = __ldg(&batch[v]);
        if (b != curb) {
            float* p = pool + (size_t)curb * 128 + lane * 4;
            atomicAdd(p, ax); atomicAdd(p + 1, ay);
            atomicAdd(p + 2, az); atomicAdd(p + 3, aw);
            if (lane == 0) atomicAdd(&pcnt[curb], cnt);
            ax = ay = az = aw = cnt = 0.f;
            curb = b;
        }
        float4 t = A4[(size_t)v * 32 + lane];
        ax += t.x; ay += t.y; az += t.z; aw += t.w;
        cnt += 1.f;
    }
    float* p = pool + (size_t)curb * 128 + lane * 4;
    atomicAdd(p, ax); atomicAdd(p + 1, ay);
    atomicAdd(p + 2, az); atomicAdd(p + 3, aw);
    if (lane == 0) atomicAdd(&pcnt[curb], cnt);
}

__global__ void k_final(const float* __restrict__ pool, const float* __restrict__ pcnt,
                        const float* __restrict__ Wlin, const float* __restrict__ blin,
                        float* __restrict__ out) {
    int b = blockIdx.x;
    int lane = threadIdx.x;
    float inv = 1.f / fmaxf(__ldg(&pcnt[b]), 1.f);
    float4 p = __ldg(&((const float4*)pool)[b * 32 + lane]);
    p.x *= inv; p.y *= inv; p.z *= inv; p.w *= inv;
    int f = lane * 4;
    #pragma unroll
    for (int c = 0; c < 10; c++) {
        float s = p.x * __ldg(&Wlin[f * 10 + c])
                + p.y * __ldg(&Wlin[(f + 1) * 10 + c])
                + p.z * __ldg(&Wlin[(f + 2) * 10 + c])
                + p.w * __ldg(&Wlin[(f + 3) * 10 + c]);
        #pragma unroll
        for (int o = 16; o; o >>= 1) s += __shfl_down_sync(0xffffffffu, s, o);
        if (lane == 0) out[b * 10 + c] = s + __ldg(&blin[c]);
    }
}

// --------------------------------- launch ----------------------------------

extern "C" void kernel_launch(void* const* d_in, const int* in_sizes, int n_in,
                              void* d_out, int out_size) {
    const float* x     = (const float*)d_in[0];
    const int*   ei    = (const int*)d_in[1];
    const int*   batch = (const int*)d_in[2];
    const float* ew    = (const float*)d_in[3];
    const float* W1 = (const float*)d_in[4];  const float* b1 = (const float*)d_in[5];
    const float* W2 = (const float*)d_in[6];  const float* b2 = (const float*)d_in[7];
    const float* W3 = (const float*)d_in[8];  const float* b3 = (const float*)d_in[9];
    const float* Wlin = (const float*)d_in[10];
    const float* blin = (const float*)d_in[11];

    int N  = in_sizes[2];        // batch has shape (N,)
    int E  = in_sizes[3];        // edge_weight has shape (E,)
    int Bg = out_size / 10;
    const int* src = ei;
    const int* dst = ei + E;

    unsigned char* base = nullptr;
    cudaGetSymbolAddress((void**)&base, g_scratch);
    __nv_bfloat16* T = (__nv_bfloat16*)(base + OFF_T);
    float* A      = (float*)(base + OFF_A);
    int2*  ed1    = (int2*)(base + OFF_ED1);
    int2*  ed     = (int2*)(base + OFF_ED);
    int*   rowptr = (int*)(base + OFF_ROWP);
    int*   cnt    = (int*)(base + OFF_CNT);
    float* deg    = (float*)(base + OFF_DEG);
    float* dinv1  = (float*)(base + OFF_DINV1);
    float* dinv   = (float*)(base + OFF_DINV);
    float* pool   = (float*)(base + OFF_POOL);
    float* pcnt   = (float*)(base + OFF_PCNT);

    cudaFuncSetAttribute(k_gemm128, cudaFuncAttributeMaxDynamicSharedMemorySize, 98304);

    const int tb = 256;
    int npad = (N + 3) & ~3;

    // CSR build (shared across all 3 layers)
    k_zero_pre<<<(npad + tb - 1) / tb, tb>>>(deg, cnt, N, npad);
    k_hist<<<(E + tb - 1) / tb, tb>>>(dst, ew, deg, cnt, E);
    k_scan<<<1, 1024>>>(cnt, rowptr, N);
    k_dinv<<<(N + tb - 1) / tb, tb>>>(deg, dinv1, dinv, N);
    k_fill<<<(E + tb - 1) / tb, tb>>>(src, dst, ew, rowptr, cnt,
                                      dinv1, dinv, ed1, ed, E);

    int gemm_blocks = (N + 63) / 64;
    int gat_blocks  = (int)(((size_t)N * 32 + 255) / 256);

    // Layer 1 (improved: fill=2.0) + ReLU
    k_gemm128<<<gemm_blocks, 256, 98304>>>(x, W1, T, N);
    k_gather<<<gat_blocks, 256>>>(T, rowptr, ed1, dinv1, 2.0f, b1, A, N, 1);
    // Layer 2 + ReLU
    k_gemm128<<<gemm_blocks, 256, 98304>>>(A, W2, T, N);
    k_gather<<<gat_blocks, 256>>>(T, rowptr, ed, dinv, 1.0f, b2, A, N, 1);
    // Layer 3 (no ReLU)
    k_gemm128<<<gemm_blocks, 256, 98304>>>(A, W3, T, N);
    k_gather<<<gat_blocks, 256>>>(T, rowptr, ed, dinv, 1.0f, b3, A, N, 0);

    // Mean pool over sorted batch ids, then linear head
    k_zero_pool<<<(Bg * 128 + tb - 1) / tb, tb>>>(pool, pcnt, Bg);
    int pw = (N + 63) / 64;
    k_pool<<<(pw * 32 + 255) / 256, 256>>>(A, batch, pool, pcnt, N);
    k_final<<<Bg, 32>>>(pool, pcnt, Wlin, blin, (float*)d_out);
}